// round 15
// baseline (speedup 1.0000x reference)
#include <cuda_runtime.h>
#include <cuda_fp16.h>

// LightGCN 3-layer propagation. CSR (dst-sorted), atomic-free reduction.
// fp16 intermediates. Props: ONE WARP PER NODE (32 lanes, half2 gathers) —
// eliminates intra-warp degree imbalance. Scalar fp32 FMA accumulate.
// Preprocessing identical to R13 (3 launches).

#define NUM_USERS 100000
#define NUM_ITEMS 50000
#define NN        150000
#define DIM       64
#define EDGES     1250000

#define NQ  (NN * 16)          // float4 count of one fp32 embedding buffer
#define UQ  (NUM_USERS * 16)

#define SCAN_B 256
#define NBLK   ((NN + SCAN_B - 1) / SCAN_B)   // 586
#define OFFSZ  (NBLK * SCAN_B)

// Device-global scratch. fp16 bufs 3x19.2MB, edges 10MB, rank 5MB.
__device__ unsigned g_embh[NN * 32];  // uw||iw fp16 (row = 32 half2 = 64 halves)
__device__ unsigned g_c1h [NN * 32];  // layer-1 result, fp16
__device__ unsigned g_c2h [NN * 32];  // layer-2 result, fp16
__device__ int      g_cnt [NN];       // in-degree (zeroed by scan after read)
__device__ float    g_rs  [NN];       // rs[x] = deg>0 ? rsqrt(deg) : 0
__device__ int      g_rank[EDGES];    // per-edge arrival rank within its dst
__device__ int      g_off [OFFSZ + 1];// block-LOCAL exclusive prefix of cnt
__device__ int      g_bsum[NBLK];     // exclusive block sums
__device__ int2     g_edge[EDGES];    // {src, __float_as_int(rs[src])} sorted by dst
__device__ int      g_done;           // last-block-done counter (self-resetting)

// ---------------------------------------------------------------------------
// Per-warp dtype detection: all warps sample the SAME first 8 int64 slots.
// ---------------------------------------------------------------------------
__device__ __forceinline__ bool detect_is32(const void* edge) {
    int lid = threadIdx.x & 31;
    bool bad = false;
    if (lid < 8) {
        long long v = ((const long long*)edge)[lid];
        bad = (v < 0 || v >= (long long)NN);
    }
    return __ballot_sync(0xffffffffu, bad) != 0;
}

// ---------------------------------------------------------------------------
// histogram + per-edge rank; grid-stride fp16 concat uw||iw -> g_embh rides
// in the atomic latency shadow.
// ---------------------------------------------------------------------------
__global__ void histrank_kernel(const void* edge,
                                const float* __restrict__ uw,
                                const float* __restrict__ iw) {
    int t = blockIdx.x * blockDim.x + threadIdx.x;
    int stride = gridDim.x * blockDim.x;
    bool is32 = detect_is32(edge);

    // fp16 concat: NQ float4 reads -> 2 half2 stores each
    uint2* eh = (uint2*)g_embh;
    for (int i = t; i < NQ; i += stride) {
        float4 v = (i < UQ) ? ((const float4*)uw)[i]
                            : ((const float4*)iw)[i - UQ];
        __half2 p0 = __floats2half2_rn(v.x, v.y);
        __half2 p1 = __floats2half2_rn(v.z, v.w);
        eh[i] = make_uint2(*reinterpret_cast<unsigned*>(&p0),
                           *reinterpret_cast<unsigned*>(&p1));
    }

    if (t >= EDGES) return;
    int d;
    if (is32) d = ((const int*)edge)[EDGES + t];
    else      d = (int)((const long long*)edge)[EDGES + t];
    g_rank[t] = atomicAdd(&g_cnt[d], 1);
}

// ---------------------------------------------------------------------------
// Fused scan: per-block exclusive scan of cnt (+ rs emit + cnt reset), then
// the LAST block to finish scans the 586 block sums (no extra launch).
// ---------------------------------------------------------------------------
__device__ __forceinline__ int warp_incl_scan(int v, int lid) {
    #pragma unroll
    for (int o = 1; o < 32; o <<= 1) {
        int t = __shfl_up_sync(0xffffffffu, v, o);
        if (lid >= o) v += t;
    }
    return v;
}

__global__ void __launch_bounds__(SCAN_B)
scan_kernel() {
    __shared__ int wsum[8];
    __shared__ int s_last;
    int b = blockIdx.x;
    int i = b * SCAN_B + threadIdx.x;
    int v = (i < NN) ? g_cnt[i] : 0;
    if (i < NN) {
        g_rs[i]  = (v > 0) ? rsqrtf((float)v) : 0.f;
        g_cnt[i] = 0;                                  // reset for next replay
    }
    int wid = threadIdx.x >> 5, lid = threadIdx.x & 31;
    int incl = warp_incl_scan(v, lid);
    if (lid == 31) wsum[wid] = incl;
    __syncthreads();
    if (wid == 0) {
        int s = (lid < 8) ? wsum[lid] : 0;
        #pragma unroll
        for (int o = 1; o < 8; o <<= 1) {
            int t = __shfl_up_sync(0xffffffffu, s, o);
            if (lid >= o) s += t;
        }
        if (lid < 8) wsum[lid] = s;
    }
    __syncthreads();
    int base = (wid > 0) ? wsum[wid - 1] : 0;
    g_off[i] = base + incl - v;                        // block-local exclusive
    if (threadIdx.x == SCAN_B - 1) g_bsum[b] = base + incl;
    if (i == 0) g_off[OFFSZ] = 0;

    __threadfence();
    if (threadIdx.x == 0) {
        int done = atomicAdd(&g_done, 1);
        s_last = (done == (int)gridDim.x - 1) ? 1 : 0;
    }
    __syncthreads();
    if (!s_last) return;

    __shared__ int wsum2[8];
    int b3 = threadIdx.x * 3;
    int a0 = (b3     < NBLK) ? g_bsum[b3]     : 0;
    int a1 = (b3 + 1 < NBLK) ? g_bsum[b3 + 1] : 0;
    int a2 = (b3 + 2 < NBLK) ? g_bsum[b3 + 2] : 0;
    int tsum = a0 + a1 + a2;
    int incl2 = warp_incl_scan(tsum, lid);
    if (lid == 31) wsum2[wid] = incl2;
    __syncthreads();
    if (wid == 0) {
        int s = (lid < 8) ? wsum2[lid] : 0;
        #pragma unroll
        for (int o = 1; o < 8; o <<= 1) {
            int t = __shfl_up_sync(0xffffffffu, s, o);
            if (lid >= o) s += t;
        }
        if (lid < 8) wsum2[lid] = s;
    }
    __syncthreads();
    int tbase = ((wid > 0) ? wsum2[wid - 1] : 0) + incl2 - tsum;
    if (b3     < NBLK) g_bsum[b3]     = tbase;
    if (b3 + 1 < NBLK) g_bsum[b3 + 1] = tbase + a0;
    if (b3 + 2 < NBLK) g_bsum[b3 + 2] = tbase + a0 + a1;
    if (threadIdx.x == 0) g_done = 0;                  // reset for next replay
}

// ---------------------------------------------------------------------------
// CSR fill: pos = local_off[d] + bsum[d>>8] + rank[e]; stores {src, rs[src]}.
// ---------------------------------------------------------------------------
__global__ void fill_kernel(const void* edge) {
    int e = blockIdx.x * blockDim.x + threadIdx.x;
    if (e >= EDGES) return;
    bool is32 = detect_is32(edge);
    int s, d;
    if (is32) {
        const int* ei = (const int*)edge;
        s = ei[e];
        d = ei[EDGES + e];
    } else {
        const long long* ei = (const long long*)edge;
        s = (int)ei[e];
        d = (int)ei[EDGES + e];
    }
    float w = g_rs[s];
    int pos = g_off[d] + g_bsum[d >> 8] + g_rank[e];
    g_edge[pos] = make_int2(s, __float_as_int(w));
}

// ---------------------------------------------------------------------------
// Propagate. ONE WARP PER NODE: lane c owns halves [2c, 2c+1] (4B half2).
// Per edge: broadcast edge load + half2 gather + 2 cvt + 2 FMA. No intra-warp
// imbalance. fp32 accumulate, scale by rs[n].
// MODE 0: nxt = result (fp16). MODE 1: out = (emb + c1 + c2 + r)/4, dup'd.
// ---------------------------------------------------------------------------
template<int MODE>
__global__ void __launch_bounds__(256)
prop_kernel(const unsigned* __restrict__ cur,
            const float* __restrict__ uw,
            const float* __restrict__ iw,
            const unsigned* __restrict__ c1,
            unsigned* __restrict__ nxt,
            float* __restrict__ out) {
    int t = blockIdx.x * blockDim.x + threadIdx.x;
    int n = t >> 5;
    int c = t & 31;
    if (n >= NN) return;
    int j   = g_off[n]     + g_bsum[n >> 8];
    int end = g_off[n + 1] + g_bsum[(n + 1) >> 8];
    float rx = 0.f, ry = 0.f;

    const int2* __restrict__ ge = g_edge;
    for (; j + 4 <= end; j += 4) {
        int2 e0 = ge[j];
        int2 e1 = ge[j + 1];
        int2 e2 = ge[j + 2];
        int2 e3 = ge[j + 3];
        unsigned v0 = cur[e0.x * 32 + c];
        unsigned v1 = cur[e1.x * 32 + c];
        unsigned v2 = cur[e2.x * 32 + c];
        unsigned v3 = cur[e3.x * 32 + c];
        float w0 = __int_as_float(e0.y), w1 = __int_as_float(e1.y);
        float w2 = __int_as_float(e2.y), w3 = __int_as_float(e3.y);
        float2 q0 = __half22float2(*reinterpret_cast<const __half2*>(&v0));
        float2 q1 = __half22float2(*reinterpret_cast<const __half2*>(&v1));
        float2 q2 = __half22float2(*reinterpret_cast<const __half2*>(&v2));
        float2 q3 = __half22float2(*reinterpret_cast<const __half2*>(&v3));
        rx += q0.x * w0 + q1.x * w1 + q2.x * w2 + q3.x * w3;
        ry += q0.y * w0 + q1.y * w1 + q2.y * w2 + q3.y * w3;
    }
    #pragma unroll 1
    for (; j < end; ++j) {
        int2 e0 = ge[j];
        unsigned v0 = cur[e0.x * 32 + c];
        float w0 = __int_as_float(e0.y);
        float2 q0 = __half22float2(*reinterpret_cast<const __half2*>(&v0));
        rx += q0.x * w0;
        ry += q0.y * w0;
    }

    float wn = g_rs[n];                    // rs[dst], broadcast
    rx *= wn; ry *= wn;

    int fo = n * 32 + c;
    if (MODE == 1) {
        float2 e = (n < NUM_USERS)
            ? ((const float2*)uw)[fo]
            : ((const float2*)iw)[fo - NUM_USERS * 32];
        unsigned u1 = c1[fo];              // layer-1 (fp16)
        unsigned u2 = cur[fo];             // layer-2 (fp16)
        float2 a = __half22float2(*reinterpret_cast<const __half2*>(&u1));
        float2 b = __half22float2(*reinterpret_cast<const __half2*>(&u2));
        float2 o;
        o.x = (e.x + a.x + b.x + rx) * 0.25f;
        o.y = (e.y + a.y + b.y + ry) * 0.25f;
        float2* op = (float2*)out;
        op[fo]           = o;
        op[NN * 32 + fo] = o;
    } else {
        __half2 p = __floats2half2_rn(rx, ry);
        nxt[fo] = *reinterpret_cast<unsigned*>(&p);
    }
}

// ---------------------------------------------------------------------------
extern "C" void kernel_launch(void* const* d_in, const int* in_sizes, int n_in,
                              void* d_out, int out_size) {
    const void*  edge = d_in[0];
    const float* uw   = (const float*)d_in[1];
    const float* iw   = (const float*)d_in[2];
    float*       out  = (float*)d_out;

    unsigned* E  = nullptr;
    unsigned* C1 = nullptr;
    unsigned* C2 = nullptr;
    cudaGetSymbolAddress((void**)&E,  g_embh);
    cudaGetSymbolAddress((void**)&C1, g_c1h);
    cudaGetSymbolAddress((void**)&C2, g_c2h);

    const int T = 256;
    const int grid_e = (EDGES + T - 1) / T;
    const int grid_p = (int)(((long long)NN * 32 + T - 1) / T);  // 1 warp/node

    histrank_kernel<<<grid_e, T>>>(edge, uw, iw);  // + fp16 concat
    scan_kernel<<<NBLK, SCAN_B>>>();               // scan1+scan2 fused
    fill_kernel<<<grid_e, T>>>(edge);

    // layer 1: emb_h -> c1_h
    prop_kernel<0><<<grid_p, T>>>(E,  uw, iw, nullptr, C1, nullptr);
    // layer 2: c1_h -> c2_h
    prop_kernel<0><<<grid_p, T>>>(C1, uw, iw, nullptr, C2, nullptr);
    // layer 3: gather c2_h; finalize with emb(fp32) + c1_h + c2_h, duplicated
    prop_kernel<1><<<grid_p, T>>>(C2, uw, iw, C1, nullptr, out);
}

// round 16
// speedup vs baseline: 1.4442x; 1.4442x over previous
#include <cuda_runtime.h>
#include <cuda_fp16.h>

// LightGCN 3-layer propagation. CSR (dst-sorted, SRC-ONLY 4B entries),
// atomic-free reduction, fp16 intermediates, 8-lane uint4 props (R13 shape).
// Pre-scaled algebra: y_k = rs*c_k stored, so the gather loop is a pure sum:
//   c_{k+1}[d] = rs[d] * sum y_k[src],  y_{k+1}[d] = rs[d]^2 * sum y_k[src].
// Finalize recovers c_k = irs*y_k (irs = sqrt(deg)).

#define NUM_USERS 100000
#define NUM_ITEMS 50000
#define NN        150000
#define DIM       64
#define EDGES     1250000

#define NQ  (NN * 16)          // float4 count of one fp32 embedding buffer
#define UQ  (NUM_USERS * 16)

#define SCAN_B 256
#define NBLK   ((NN + SCAN_B - 1) / SCAN_B)   // 586
#define OFFSZ  (NBLK * SCAN_B)

// Device-global scratch. fp16 bufs 3x19.2MB, srcs 5MB, rank 5MB.
__device__ uint4 g_embh[NN * 8];    // y0 = rs*emb, fp16 (row = 8 uint4)
__device__ uint4 g_c1h [NN * 8];    // y1, fp16
__device__ uint4 g_c2h [NN * 8];    // y2, fp16
__device__ int   g_cnt [NN];        // in-degree (zeroed by scan after read)
__device__ float g_rs  [NN];        // rs[x] = deg>0 ? rsqrt(deg) : 0
__device__ float g_irs [NN];        // irs[x] = deg>0 ? sqrt(deg) : 0
__device__ int   g_rank[EDGES];     // per-edge arrival rank within its dst
__device__ int   g_off [OFFSZ + 1]; // block-LOCAL exclusive prefix of cnt
__device__ int   g_bsum[NBLK];      // exclusive block sums
__device__ int   g_srcs[EDGES];     // src per edge, sorted by dst (4B!)
__device__ int   g_done;            // last-block-done counter (self-resetting)

// ---------------------------------------------------------------------------
// Per-warp dtype detection: all warps sample the SAME first 8 int64 slots.
// ---------------------------------------------------------------------------
__device__ __forceinline__ bool detect_is32(const void* edge) {
    int lid = threadIdx.x & 31;
    bool bad = false;
    if (lid < 8) {
        long long v = ((const long long*)edge)[lid];
        bad = (v < 0 || v >= (long long)NN);
    }
    return __ballot_sync(0xffffffffu, bad) != 0;
}

// ---------------------------------------------------------------------------
// histogram + per-edge rank (no concat here anymore — it needs rs).
// ---------------------------------------------------------------------------
__global__ void histrank_kernel(const void* edge) {
    int t = blockIdx.x * blockDim.x + threadIdx.x;
    if (t >= EDGES) return;
    bool is32 = detect_is32(edge);
    int d;
    if (is32) d = ((const int*)edge)[EDGES + t];
    else      d = (int)((const long long*)edge)[EDGES + t];
    g_rank[t] = atomicAdd(&g_cnt[d], 1);
}

// ---------------------------------------------------------------------------
// Fused scan: per-block exclusive scan of cnt (+ rs/irs emit + cnt reset),
// then the LAST block to finish scans the 586 block sums (no extra launch).
// ---------------------------------------------------------------------------
__device__ __forceinline__ int warp_incl_scan(int v, int lid) {
    #pragma unroll
    for (int o = 1; o < 32; o <<= 1) {
        int t = __shfl_up_sync(0xffffffffu, v, o);
        if (lid >= o) v += t;
    }
    return v;
}

__global__ void __launch_bounds__(SCAN_B)
scan_kernel() {
    __shared__ int wsum[8];
    __shared__ int s_last;
    int b = blockIdx.x;
    int i = b * SCAN_B + threadIdx.x;
    int v = (i < NN) ? g_cnt[i] : 0;
    if (i < NN) {
        float fv = (float)v;
        g_rs[i]  = (v > 0) ? rsqrtf(fv) : 0.f;
        g_irs[i] = (v > 0) ? sqrtf(fv)  : 0.f;
        g_cnt[i] = 0;                                  // reset for next replay
    }
    int wid = threadIdx.x >> 5, lid = threadIdx.x & 31;
    int incl = warp_incl_scan(v, lid);
    if (lid == 31) wsum[wid] = incl;
    __syncthreads();
    if (wid == 0) {
        int s = (lid < 8) ? wsum[lid] : 0;
        #pragma unroll
        for (int o = 1; o < 8; o <<= 1) {
            int t = __shfl_up_sync(0xffffffffu, s, o);
            if (lid >= o) s += t;
        }
        if (lid < 8) wsum[lid] = s;
    }
    __syncthreads();
    int base = (wid > 0) ? wsum[wid - 1] : 0;
    g_off[i] = base + incl - v;                        // block-local exclusive
    if (threadIdx.x == SCAN_B - 1) g_bsum[b] = base + incl;
    if (i == 0) g_off[OFFSZ] = 0;

    __threadfence();
    if (threadIdx.x == 0) {
        int done = atomicAdd(&g_done, 1);
        s_last = (done == (int)gridDim.x - 1) ? 1 : 0;
    }
    __syncthreads();
    if (!s_last) return;

    __shared__ int wsum2[8];
    int b3 = threadIdx.x * 3;
    int a0 = (b3     < NBLK) ? g_bsum[b3]     : 0;
    int a1 = (b3 + 1 < NBLK) ? g_bsum[b3 + 1] : 0;
    int a2 = (b3 + 2 < NBLK) ? g_bsum[b3 + 2] : 0;
    int tsum = a0 + a1 + a2;
    int incl2 = warp_incl_scan(tsum, lid);
    if (lid == 31) wsum2[wid] = incl2;
    __syncthreads();
    if (wid == 0) {
        int s = (lid < 8) ? wsum2[lid] : 0;
        #pragma unroll
        for (int o = 1; o < 8; o <<= 1) {
            int t = __shfl_up_sync(0xffffffffu, s, o);
            if (lid >= o) s += t;
        }
        if (lid < 8) wsum2[lid] = s;
    }
    __syncthreads();
    int tbase = ((wid > 0) ? wsum2[wid - 1] : 0) + incl2 - tsum;
    if (b3     < NBLK) g_bsum[b3]     = tbase;
    if (b3 + 1 < NBLK) g_bsum[b3 + 1] = tbase + a0;
    if (b3 + 2 < NBLK) g_bsum[b3 + 2] = tbase + a0 + a1;
    if (threadIdx.x == 0) g_done = 0;                  // reset for next replay
}

// ---------------------------------------------------------------------------
// CSR fill (src only) + grid-stride pre-scaled fp16 concat y0 = rs*(uw||iw).
// ---------------------------------------------------------------------------
__global__ void fill_kernel(const void* edge,
                            const float* __restrict__ uw,
                            const float* __restrict__ iw) {
    int t = blockIdx.x * blockDim.x + threadIdx.x;
    int stride = gridDim.x * blockDim.x;
    bool is32 = detect_is32(edge);

    // y0 concat: NQ float4 reads, scaled by rs[node], stored fp16
    uint2* eh = (uint2*)g_embh;
    for (int i = t; i < NQ; i += stride) {
        float4 v = (i < UQ) ? ((const float4*)uw)[i]
                            : ((const float4*)iw)[i - UQ];
        float w = g_rs[i >> 4];            // node = float4_index / 16
        __half2 p0 = __floats2half2_rn(v.x * w, v.y * w);
        __half2 p1 = __floats2half2_rn(v.z * w, v.w * w);
        eh[i] = make_uint2(*reinterpret_cast<unsigned*>(&p0),
                           *reinterpret_cast<unsigned*>(&p1));
    }

    if (t >= EDGES) return;
    int s, d;
    if (is32) {
        const int* ei = (const int*)edge;
        s = ei[t];
        d = ei[EDGES + t];
    } else {
        const long long* ei = (const long long*)edge;
        s = (int)ei[t];
        d = (int)ei[EDGES + t];
    }
    int pos = g_off[d] + g_bsum[d >> 8] + g_rank[t];
    g_srcs[pos] = s;
}

// ---------------------------------------------------------------------------
// Propagate (R13 shape). 8 lanes per node; lane c owns halves [8c..8c+7].
// Pure unweighted sum of fp16 rows, fp32 accumulate.
// MODE 0: nxt = fp16(rs[n]^2 * S).
// MODE 1: out = (emb + irs*y1 + irs*y2 + rs*S)/4, duplicated.
// ---------------------------------------------------------------------------
__device__ __forceinline__ void add_h8(float4& ra, float4& rb, uint4 v) {
    float2 q0 = __half22float2(*reinterpret_cast<const __half2*>(&v.x));
    float2 q1 = __half22float2(*reinterpret_cast<const __half2*>(&v.y));
    float2 q2 = __half22float2(*reinterpret_cast<const __half2*>(&v.z));
    float2 q3 = __half22float2(*reinterpret_cast<const __half2*>(&v.w));
    ra.x += q0.x; ra.y += q0.y; ra.z += q1.x; ra.w += q1.y;
    rb.x += q2.x; rb.y += q2.y; rb.z += q3.x; rb.w += q3.y;
}

template<int MODE>
__global__ void __launch_bounds__(256)
prop_kernel(const uint4* __restrict__ cur,
            const float* __restrict__ uw,
            const float* __restrict__ iw,
            const uint4* __restrict__ c1,
            uint4* __restrict__ nxt,
            float* __restrict__ out) {
    int t = blockIdx.x * blockDim.x + threadIdx.x;
    int n = t >> 3;
    int c = t & 7;
    if (n >= NN) return;
    int j   = g_off[n]     + g_bsum[n >> 8];
    int end = g_off[n + 1] + g_bsum[(n + 1) >> 8];
    float4 ra = make_float4(0.f, 0.f, 0.f, 0.f);
    float4 rb = make_float4(0.f, 0.f, 0.f, 0.f);

    const int* __restrict__ gs = g_srcs;
    for (; j + 4 <= end; j += 4) {
        int s0 = gs[j];
        int s1 = gs[j + 1];
        int s2 = gs[j + 2];
        int s3 = gs[j + 3];
        uint4 v0 = cur[s0 * 8 + c];
        uint4 v1 = cur[s1 * 8 + c];
        uint4 v2 = cur[s2 * 8 + c];
        uint4 v3 = cur[s3 * 8 + c];
        add_h8(ra, rb, v0);
        add_h8(ra, rb, v1);
        add_h8(ra, rb, v2);
        add_h8(ra, rb, v3);
    }
    #pragma unroll 1
    for (; j < end; ++j) {
        uint4 v0 = cur[gs[j] * 8 + c];
        add_h8(ra, rb, v0);
    }

    float wn = g_rs[n];                    // rs[dst]
    if (MODE == 1) {
        // c3 = rs*S ; c1 = irs*y1 ; c2 = irs*y2 ; out = (emb+c1+c2+c3)/4
        float wi = g_irs[n];
        int fo = n * 16 + c * 2;
        const float4* ew = (n < NUM_USERS) ? (const float4*)uw
                                           : (const float4*)iw - UQ;
        float4 ea = ew[fo];
        float4 eb = ew[fo + 1];
        uint4 u1 = c1[n * 8 + c];          // y1 (fp16)
        uint4 u2 = cur[n * 8 + c];         // y2 (fp16)
        float4 za = make_float4(0.f, 0.f, 0.f, 0.f);
        float4 zb = make_float4(0.f, 0.f, 0.f, 0.f);
        add_h8(za, zb, u1);                // za/zb = y1 + y2 (per slot)
        add_h8(za, zb, u2);
        float4 oa, ob;
        oa.x = (ea.x + wi * za.x + wn * ra.x) * 0.25f;
        oa.y = (ea.y + wi * za.y + wn * ra.y) * 0.25f;
        oa.z = (ea.z + wi * za.z + wn * ra.z) * 0.25f;
        oa.w = (ea.w + wi * za.w + wn * ra.w) * 0.25f;
        ob.x = (eb.x + wi * zb.x + wn * rb.x) * 0.25f;
        ob.y = (eb.y + wi * zb.y + wn * rb.y) * 0.25f;
        ob.z = (eb.z + wi * zb.z + wn * rb.z) * 0.25f;
        ob.w = (eb.w + wi * zb.w + wn * rb.w) * 0.25f;
        float4* op = (float4*)out;
        op[fo]          = oa;
        op[fo + 1]      = ob;
        op[NQ + fo]     = oa;
        op[NQ + fo + 1] = ob;
    } else {
        float w2 = wn * wn;                // y_next = rs^2 * S
        __half2 p0 = __floats2half2_rn(ra.x * w2, ra.y * w2);
        __half2 p1 = __floats2half2_rn(ra.z * w2, ra.w * w2);
        __half2 p2 = __floats2half2_rn(rb.x * w2, rb.y * w2);
        __half2 p3 = __floats2half2_rn(rb.z * w2, rb.w * w2);
        nxt[n * 8 + c] = make_uint4(*reinterpret_cast<unsigned*>(&p0),
                                    *reinterpret_cast<unsigned*>(&p1),
                                    *reinterpret_cast<unsigned*>(&p2),
                                    *reinterpret_cast<unsigned*>(&p3));
    }
}

// ---------------------------------------------------------------------------
extern "C" void kernel_launch(void* const* d_in, const int* in_sizes, int n_in,
                              void* d_out, int out_size) {
    const void*  edge = d_in[0];
    const float* uw   = (const float*)d_in[1];
    const float* iw   = (const float*)d_in[2];
    float*       out  = (float*)d_out;

    uint4* E  = nullptr;
    uint4* C1 = nullptr;
    uint4* C2 = nullptr;
    cudaGetSymbolAddress((void**)&E,  g_embh);
    cudaGetSymbolAddress((void**)&C1, g_c1h);
    cudaGetSymbolAddress((void**)&C2, g_c2h);

    const int T = 256;
    const int grid_e = (EDGES + T - 1) / T;
    const int grid_p = (NN * 8 + T - 1) / T;   // 8 lanes/node

    histrank_kernel<<<grid_e, T>>>(edge);
    scan_kernel<<<NBLK, SCAN_B>>>();               // + rs/irs + cnt reset
    fill_kernel<<<grid_e, T>>>(edge, uw, iw);      // + pre-scaled y0 concat

    // layer 1: y0 -> y1
    prop_kernel<0><<<grid_p, T>>>(E,  uw, iw, nullptr, C1, nullptr);
    // layer 2: y1 -> y2
    prop_kernel<0><<<grid_p, T>>>(C1, uw, iw, nullptr, C2, nullptr);
    // layer 3: gather y2; finalize out = (emb + irs*(y1+y2) + rs*S)/4, dup'd
    prop_kernel<1><<<grid_p, T>>>(C2, uw, iw, C1, nullptr, out);
}

// round 17
// speedup vs baseline: 1.5487x; 1.0724x over previous
#include <cuda_runtime.h>
#include <cuda_fp16.h>

// LightGCN 3-layer propagation. CSR (dst-sorted, src-only), atomic-free,
// fp16 intermediates, pre-scaled algebra (pure-sum gather loop).
// NEW vs R16: adjacent edge pairs are summed in fp16 (HADD2) before the
// fp32 convert+accumulate — ~37% fewer arithmetic issue slots in the loop.

#define NUM_USERS 100000
#define NUM_ITEMS 50000
#define NN        150000
#define DIM       64
#define EDGES     1250000

#define NQ  (NN * 16)          // float4 count of one fp32 embedding buffer
#define UQ  (NUM_USERS * 16)

#define SCAN_B 256
#define NBLK   ((NN + SCAN_B - 1) / SCAN_B)   // 586
#define OFFSZ  (NBLK * SCAN_B)

// Device-global scratch. fp16 bufs 3x19.2MB, srcs 5MB, rank 5MB.
__device__ uint4 g_embh[NN * 8];    // y0 = rs*emb, fp16 (row = 8 uint4)
__device__ uint4 g_c1h [NN * 8];    // y1, fp16
__device__ uint4 g_c2h [NN * 8];    // y2, fp16
__device__ int   g_cnt [NN];        // in-degree (zeroed by scan after read)
__device__ float g_rs  [NN];        // rs[x] = deg>0 ? rsqrt(deg) : 0
__device__ float g_irs [NN];        // irs[x] = deg>0 ? sqrt(deg) : 0
__device__ int   g_rank[EDGES];     // per-edge arrival rank within its dst
__device__ int   g_off [OFFSZ + 1]; // block-LOCAL exclusive prefix of cnt
__device__ int   g_bsum[NBLK];      // exclusive block sums
__device__ int   g_srcs[EDGES];     // src per edge, sorted by dst (4B)
__device__ int   g_done;            // last-block-done counter (self-resetting)

// ---------------------------------------------------------------------------
// Per-warp dtype detection: all warps sample the SAME first 8 int64 slots.
// ---------------------------------------------------------------------------
__device__ __forceinline__ bool detect_is32(const void* edge) {
    int lid = threadIdx.x & 31;
    bool bad = false;
    if (lid < 8) {
        long long v = ((const long long*)edge)[lid];
        bad = (v < 0 || v >= (long long)NN);
    }
    return __ballot_sync(0xffffffffu, bad) != 0;
}

// ---------------------------------------------------------------------------
// histogram + per-edge rank
// ---------------------------------------------------------------------------
__global__ void histrank_kernel(const void* edge) {
    int t = blockIdx.x * blockDim.x + threadIdx.x;
    if (t >= EDGES) return;
    bool is32 = detect_is32(edge);
    int d;
    if (is32) d = ((const int*)edge)[EDGES + t];
    else      d = (int)((const long long*)edge)[EDGES + t];
    g_rank[t] = atomicAdd(&g_cnt[d], 1);
}

// ---------------------------------------------------------------------------
// Fused scan: per-block exclusive scan of cnt (+ rs/irs emit + cnt reset),
// then the LAST block to finish scans the 586 block sums (no extra launch).
// ---------------------------------------------------------------------------
__device__ __forceinline__ int warp_incl_scan(int v, int lid) {
    #pragma unroll
    for (int o = 1; o < 32; o <<= 1) {
        int t = __shfl_up_sync(0xffffffffu, v, o);
        if (lid >= o) v += t;
    }
    return v;
}

__global__ void __launch_bounds__(SCAN_B)
scan_kernel() {
    __shared__ int wsum[8];
    __shared__ int s_last;
    int b = blockIdx.x;
    int i = b * SCAN_B + threadIdx.x;
    int v = (i < NN) ? g_cnt[i] : 0;
    if (i < NN) {
        float fv = (float)v;
        g_rs[i]  = (v > 0) ? rsqrtf(fv) : 0.f;
        g_irs[i] = (v > 0) ? sqrtf(fv)  : 0.f;
        g_cnt[i] = 0;                                  // reset for next replay
    }
    int wid = threadIdx.x >> 5, lid = threadIdx.x & 31;
    int incl = warp_incl_scan(v, lid);
    if (lid == 31) wsum[wid] = incl;
    __syncthreads();
    if (wid == 0) {
        int s = (lid < 8) ? wsum[lid] : 0;
        #pragma unroll
        for (int o = 1; o < 8; o <<= 1) {
            int t = __shfl_up_sync(0xffffffffu, s, o);
            if (lid >= o) s += t;
        }
        if (lid < 8) wsum[lid] = s;
    }
    __syncthreads();
    int base = (wid > 0) ? wsum[wid - 1] : 0;
    g_off[i] = base + incl - v;                        // block-local exclusive
    if (threadIdx.x == SCAN_B - 1) g_bsum[b] = base + incl;
    if (i == 0) g_off[OFFSZ] = 0;

    __threadfence();
    if (threadIdx.x == 0) {
        int done = atomicAdd(&g_done, 1);
        s_last = (done == (int)gridDim.x - 1) ? 1 : 0;
    }
    __syncthreads();
    if (!s_last) return;

    __shared__ int wsum2[8];
    int b3 = threadIdx.x * 3;
    int a0 = (b3     < NBLK) ? g_bsum[b3]     : 0;
    int a1 = (b3 + 1 < NBLK) ? g_bsum[b3 + 1] : 0;
    int a2 = (b3 + 2 < NBLK) ? g_bsum[b3 + 2] : 0;
    int tsum = a0 + a1 + a2;
    int incl2 = warp_incl_scan(tsum, lid);
    if (lid == 31) wsum2[wid] = incl2;
    __syncthreads();
    if (wid == 0) {
        int s = (lid < 8) ? wsum2[lid] : 0;
        #pragma unroll
        for (int o = 1; o < 8; o <<= 1) {
            int t = __shfl_up_sync(0xffffffffu, s, o);
            if (lid >= o) s += t;
        }
        if (lid < 8) wsum2[lid] = s;
    }
    __syncthreads();
    int tbase = ((wid > 0) ? wsum2[wid - 1] : 0) + incl2 - tsum;
    if (b3     < NBLK) g_bsum[b3]     = tbase;
    if (b3 + 1 < NBLK) g_bsum[b3 + 1] = tbase + a0;
    if (b3 + 2 < NBLK) g_bsum[b3 + 2] = tbase + a0 + a1;
    if (threadIdx.x == 0) g_done = 0;                  // reset for next replay
}

// ---------------------------------------------------------------------------
// CSR fill (src only) + grid-stride pre-scaled fp16 concat y0 = rs*(uw||iw).
// ---------------------------------------------------------------------------
__global__ void fill_kernel(const void* edge,
                            const float* __restrict__ uw,
                            const float* __restrict__ iw) {
    int t = blockIdx.x * blockDim.x + threadIdx.x;
    int stride = gridDim.x * blockDim.x;
    bool is32 = detect_is32(edge);

    uint2* eh = (uint2*)g_embh;
    for (int i = t; i < NQ; i += stride) {
        float4 v = (i < UQ) ? ((const float4*)uw)[i]
                            : ((const float4*)iw)[i - UQ];
        float w = g_rs[i >> 4];
        __half2 p0 = __floats2half2_rn(v.x * w, v.y * w);
        __half2 p1 = __floats2half2_rn(v.z * w, v.w * w);
        eh[i] = make_uint2(*reinterpret_cast<unsigned*>(&p0),
                           *reinterpret_cast<unsigned*>(&p1));
    }

    if (t >= EDGES) return;
    int s, d;
    if (is32) {
        const int* ei = (const int*)edge;
        s = ei[t];
        d = ei[EDGES + t];
    } else {
        const long long* ei = (const long long*)edge;
        s = (int)ei[t];
        d = (int)ei[EDGES + t];
    }
    int pos = g_off[d] + g_bsum[d >> 8] + g_rank[t];
    g_srcs[pos] = s;
}

// ---------------------------------------------------------------------------
// fp16 helpers
// ---------------------------------------------------------------------------
__device__ __forceinline__ unsigned hadd2u(unsigned a, unsigned b) {
    __half2 r = __hadd2(*reinterpret_cast<const __half2*>(&a),
                        *reinterpret_cast<const __half2*>(&b));
    return *reinterpret_cast<unsigned*>(&r);
}
__device__ __forceinline__ uint4 hadd2u4(uint4 a, uint4 b) {
    return make_uint4(hadd2u(a.x, b.x), hadd2u(a.y, b.y),
                      hadd2u(a.z, b.z), hadd2u(a.w, b.w));
}
__device__ __forceinline__ void add_h8(float4& ra, float4& rb, uint4 v) {
    float2 q0 = __half22float2(*reinterpret_cast<const __half2*>(&v.x));
    float2 q1 = __half22float2(*reinterpret_cast<const __half2*>(&v.y));
    float2 q2 = __half22float2(*reinterpret_cast<const __half2*>(&v.z));
    float2 q3 = __half22float2(*reinterpret_cast<const __half2*>(&v.w));
    ra.x += q0.x; ra.y += q0.y; ra.z += q1.x; ra.w += q1.y;
    rb.x += q2.x; rb.y += q2.y; rb.z += q3.x; rb.w += q3.y;
}

// ---------------------------------------------------------------------------
// Propagate. 8 lanes per node; lane c owns halves [8c..8c+7] (16B uint4).
// Edge pairs summed in fp16 (HADD2) before fp32 convert+accumulate.
// MODE 0: nxt = fp16(rs[n]^2 * S).
// MODE 1: out = (emb + irs*(y1+y2) + rs*S)/4, duplicated.
// ---------------------------------------------------------------------------
template<int MODE>
__global__ void __launch_bounds__(256)
prop_kernel(const uint4* __restrict__ cur,
            const float* __restrict__ uw,
            const float* __restrict__ iw,
            const uint4* __restrict__ c1,
            uint4* __restrict__ nxt,
            float* __restrict__ out) {
    int t = blockIdx.x * blockDim.x + threadIdx.x;
    int n = t >> 3;
    int c = t & 7;
    if (n >= NN) return;
    int j   = g_off[n]     + g_bsum[n >> 8];
    int end = g_off[n + 1] + g_bsum[(n + 1) >> 8];
    float4 ra = make_float4(0.f, 0.f, 0.f, 0.f);
    float4 rb = make_float4(0.f, 0.f, 0.f, 0.f);

    const int* __restrict__ gs = g_srcs;
    for (; j + 4 <= end; j += 4) {
        int s0 = gs[j];
        int s1 = gs[j + 1];
        int s2 = gs[j + 2];
        int s3 = gs[j + 3];
        uint4 v0 = cur[s0 * 8 + c];
        uint4 v1 = cur[s1 * 8 + c];
        uint4 v2 = cur[s2 * 8 + c];
        uint4 v3 = cur[s3 * 8 + c];
        uint4 p01 = hadd2u4(v0, v1);       // fp16 pair sums
        uint4 p23 = hadd2u4(v2, v3);
        add_h8(ra, rb, p01);
        add_h8(ra, rb, p23);
    }
    #pragma unroll 1
    for (; j < end; ++j) {
        uint4 v0 = cur[gs[j] * 8 + c];
        add_h8(ra, rb, v0);
    }

    float wn = g_rs[n];                    // rs[dst]
    if (MODE == 1) {
        float wi = g_irs[n];
        int fo = n * 16 + c * 2;
        const float4* ew = (n < NUM_USERS) ? (const float4*)uw
                                           : (const float4*)iw - UQ;
        float4 ea = ew[fo];
        float4 eb = ew[fo + 1];
        uint4 u1 = c1[n * 8 + c];          // y1 (fp16)
        uint4 u2 = cur[n * 8 + c];         // y2 (fp16)
        float4 za = make_float4(0.f, 0.f, 0.f, 0.f);
        float4 zb = make_float4(0.f, 0.f, 0.f, 0.f);
        add_h8(za, zb, u1);
        add_h8(za, zb, u2);
        float4 oa, ob;
        oa.x = (ea.x + wi * za.x + wn * ra.x) * 0.25f;
        oa.y = (ea.y + wi * za.y + wn * ra.y) * 0.25f;
        oa.z = (ea.z + wi * za.z + wn * ra.z) * 0.25f;
        oa.w = (ea.w + wi * za.w + wn * ra.w) * 0.25f;
        ob.x = (eb.x + wi * zb.x + wn * rb.x) * 0.25f;
        ob.y = (eb.y + wi * zb.y + wn * rb.y) * 0.25f;
        ob.z = (eb.z + wi * zb.z + wn * rb.z) * 0.25f;
        ob.w = (eb.w + wi * zb.w + wn * rb.w) * 0.25f;
        float4* op = (float4*)out;
        op[fo]          = oa;
        op[fo + 1]      = ob;
        op[NQ + fo]     = oa;
        op[NQ + fo + 1] = ob;
    } else {
        float w2 = wn * wn;                // y_next = rs^2 * S
        __half2 p0 = __floats2half2_rn(ra.x * w2, ra.y * w2);
        __half2 p1 = __floats2half2_rn(ra.z * w2, ra.w * w2);
        __half2 p2 = __floats2half2_rn(rb.x * w2, rb.y * w2);
        __half2 p3 = __floats2half2_rn(rb.z * w2, rb.w * w2);
        nxt[n * 8 + c] = make_uint4(*reinterpret_cast<unsigned*>(&p0),
                                    *reinterpret_cast<unsigned*>(&p1),
                                    *reinterpret_cast<unsigned*>(&p2),
                                    *reinterpret_cast<unsigned*>(&p3));
    }
}

// ---------------------------------------------------------------------------
extern "C" void kernel_launch(void* const* d_in, const int* in_sizes, int n_in,
                              void* d_out, int out_size) {
    const void*  edge = d_in[0];
    const float* uw   = (const float*)d_in[1];
    const float* iw   = (const float*)d_in[2];
    float*       out  = (float*)d_out;

    uint4* E  = nullptr;
    uint4* C1 = nullptr;
    uint4* C2 = nullptr;
    cudaGetSymbolAddress((void**)&E,  g_embh);
    cudaGetSymbolAddress((void**)&C1, g_c1h);
    cudaGetSymbolAddress((void**)&C2, g_c2h);

    const int T = 256;
    const int grid_e = (EDGES + T - 1) / T;
    const int grid_p = (NN * 8 + T - 1) / T;   // 8 lanes/node

    histrank_kernel<<<grid_e, T>>>(edge);
    scan_kernel<<<NBLK, SCAN_B>>>();               // + rs/irs + cnt reset
    fill_kernel<<<grid_e, T>>>(edge, uw, iw);      // + pre-scaled y0 concat

    // layer 1: y0 -> y1
    prop_kernel<0><<<grid_p, T>>>(E,  uw, iw, nullptr, C1, nullptr);
    // layer 2: y1 -> y2
    prop_kernel<0><<<grid_p, T>>>(C1, uw, iw, nullptr, C2, nullptr);
    // layer 3: gather y2; finalize out = (emb + irs*(y1+y2) + rs*S)/4, dup'd
    prop_kernel<1><<<grid_p, T>>>(C2, uw, iw, C1, nullptr, out);
}